// round 11
// baseline (speedup 1.0000x reference)
#include <cuda_runtime.h>
#include <cuda_fp16.h>
#include <math.h>
#include <stdint.h>

// Problem constants
#define BB 32
#define TT 32
#define AD 32
#define HID 1536
#define K2 (2*HID)   // 3072

// Scratch (__device__ globals)
__device__ __half g_xf[BB*TT*K2];    // concat([a_emb, tau]) fp16
__device__ __half g_hf[BB*TT*HID];   // swish hidden fp16
__device__ int g_gcat[32];
__device__ int g_gsamp[32][2];
__device__ int g_ngroups;

// ---------------------------------------------------------------------------
// Setup: group samples by cat in pairs. One warp.
// ---------------------------------------------------------------------------
__global__ void setup_groups(const int* __restrict__ cats)
{
    __shared__ int sc[32];
    int t = threadIdx.x;
    sc[t] = cats[t];
    __syncwarp();

    unsigned mask = 0;
    #pragma unroll
    for (int s = 0; s < 32; s++)
        if (sc[s] == t) mask |= (1u << s);
    int cnt = __popc(mask);
    int ng  = (cnt + 1) >> 1;

    int incl = ng;
    #pragma unroll
    for (int off = 1; off < 32; off <<= 1) {
        int v = __shfl_up_sync(0xffffffffu, incl, off);
        if (t >= off) incl += v;
    }
    int pre   = incl - ng;
    int total = __shfl_sync(0xffffffffu, incl, 31);
    if (t == 0) g_ngroups = total;

    unsigned m = mask;
    for (int g = 0; g < ng; g++) {
        int slot = pre + g;
        g_gcat[slot] = t;
        #pragma unroll
        for (int j = 0; j < 2; j++) {
            int s = -1;
            if (m) { s = __ffs(m) - 1; m &= m - 1; }
            g_gsamp[slot][j] = s;
        }
    }
    for (int slot = total + t; slot < 32; slot += 32) {
        g_gcat[slot] = -1;
        g_gsamp[slot][0] = -1;
        g_gsamp[slot][1] = -1;
    }
}

// ---------------------------------------------------------------------------
// Kernel 1: x = [actions @ W1[cat] + b1, sinusoidal(ts)] -> fp16
// ---------------------------------------------------------------------------
__global__ __launch_bounds__(256) void embed_kernel(
    const float* __restrict__ actions,
    const int*   __restrict__ timesteps,
    const int*   __restrict__ cats,
    const float* __restrict__ W1,
    const float* __restrict__ b1)
{
    int b = blockIdx.x;
    int p = blockIdx.y * 256 + threadIdx.x;
    int j = 2 * p;

    __shared__ float sa[TT*AD];
    for (int i = threadIdx.x; i < TT*AD; i += 256)
        sa[i] = actions[(size_t)b*TT*AD + i];
    __syncthreads();

    int cat = cats[b];
    const float* Wc = W1 + (size_t)cat * AD * HID;
    float2 bb = *reinterpret_cast<const float2*>(&b1[(size_t)cat*HID + j]);

    float2 wv[AD];
    #pragma unroll
    for (int k = 0; k < AD; k++)
        wv[k] = *reinterpret_cast<const float2*>(&Wc[(size_t)k*HID + j]);

    const float C = -9.210340371976184f / 768.0f;
    float ts = (float)timesteps[b];
    float freq = expf(C * (float)p);
    float s, c;
    sincosf(ts * freq, &s, &c);
    __half2 tp = __floats2half2_rn(s, c);
    uint32_t tu = *reinterpret_cast<uint32_t*>(&tp);

    #pragma unroll 4
    for (int t = 0; t < TT; t++) {
        float a0 = bb.x, a1 = bb.y;
        #pragma unroll
        for (int k = 0; k < AD; k++) {
            float av = sa[t*AD + k];
            a0 += av * wv[k].x;
            a1 += av * wv[k].y;
        }
        size_t row = (size_t)(b*TT + t) * K2;
        __half2 ap = __floats2half2_rn(a0, a1);
        *reinterpret_cast<uint32_t*>(&g_xf[row + j]) = *reinterpret_cast<uint32_t*>(&ap);
        *reinterpret_cast<uint32_t*>(&g_xf[row + HID + j]) = tu;
    }
}

// ---------------------------------------------------------------------------
// Grouped fp16 mma.sync GEMM.
// CTA: M=64 (2 samples, one cat) x N=64, K-tile 32. 8 warps, warp = 32r x 16c.
// X fp16: 3-stage cp.async ring (pad-40 rows).
// W fp32: 2-stage cp.async ring (SW128-swizzled 256B rows); each thread loads
//   2 consecutive 16B chunks (addresses swizzled INDEPENDENTLY) and converts
//   with 2xLDS.128 + 1xSTS.128 into sWc (2-stage, pad-72 rows).
// ONE __syncthreads per k-tile. Target 5 CTAs/SM.
// ---------------------------------------------------------------------------
#define GN    64
#define PADX  40
#define PADW  72
#define XELEM (64*PADX)          // 2560 fp16 per stage
#define WCS   (32*PADW)          // 2304 fp16 per stage
#define OX(s)   ((s)*(XELEM*2))                 // 3 x 5120
#define OWF(s)  (15360 + (s)*8192)              // 2 x 8192
#define OWC(s)  (31744 + (s)*(WCS*2))           // 2 x 4608
#define SMEM_BYTES 40960

#define SWZ(o) ((o) ^ (((o) >> 3) & 0x70))

#define MMA_F16(d, a0,a1,a2,a3, b0,b1) \
  asm volatile("mma.sync.aligned.m16n8k16.row.col.f32.f16.f16.f32 " \
               "{%0,%1,%2,%3}, {%4,%5,%6,%7}, {%8,%9}, {%0,%1,%2,%3};" \
               : "+f"(d[0]),"+f"(d[1]),"+f"(d[2]),"+f"(d[3]) \
               : "r"(a0),"r"(a1),"r"(a2),"r"(a3),"r"(b0),"r"(b1))

#define LDSM_X4(r0,r1,r2,r3, addr) \
  asm volatile("ldmatrix.sync.aligned.m8n8.x4.shared.b16 {%0,%1,%2,%3}, [%4];" \
               : "=r"(r0),"=r"(r1),"=r"(r2),"=r"(r3) : "r"(addr))

#define LDSM_X2T(r0,r1, addr) \
  asm volatile("ldmatrix.sync.aligned.m8n8.x2.trans.shared.b16 {%0,%1}, [%2];" \
               : "=r"(r0),"=r"(r1) : "r"(addr))

#define CP16(sa, ga, sz) \
  asm volatile("cp.async.ca.shared.global [%0], [%1], 16, %2;" \
               :: "r"(sa), "l"(ga), "r"(sz))
#define CP16F(sa, ga) \
  asm volatile("cp.async.ca.shared.global [%0], [%1], 16;" :: "r"(sa), "l"(ga))
#define CP_COMMIT() asm volatile("cp.async.commit_group;" ::: "memory")

__global__ __launch_bounds__(256,5) void gemm_grouped(
    const __half* __restrict__ Xf,
    const float* __restrict__ W,
    const float* __restrict__ bias,
    float* __restrict__ Yf32,
    int K, int writeH)
{
    if ((int)blockIdx.y >= g_ngroups) return;

    extern __shared__ char smem[];
    uint32_t sb;
    asm("{ .reg .u64 t; cvta.to.shared.u64 t, %1; cvt.u32.u64 %0, t; }"
        : "=r"(sb) : "l"(smem));

    int slot = blockIdx.y;
    int cat  = g_gcat[slot];
    int s0 = g_gsamp[slot][0];
    int s1 = g_gsamp[slot][1];

    int n0 = blockIdx.x * GN;

    int tid  = threadIdx.x;
    int lane = tid & 31;
    int warp = tid >> 5;
    int mrow = warp & 1;
    int ncol = warp >> 1;

    int lr15 = lane & 15;
    int hiK8 = ((lane >> 4) & 1) * 8;
    int mysamp = mrow ? s1 : s0;
    bool active = (mysamp >= 0);

    float acc[2][2][4];
    #pragma unroll
    for (int mt = 0; mt < 2; mt++)
        #pragma unroll
        for (int nt = 0; nt < 2; nt++)
            #pragma unroll
            for (int j = 0; j < 4; j++) acc[mt][nt][j] = 0.0f;

    // ---- staging geometry ----
    // X: 64 rows x 32 k fp16 = 256 x 16B chunks, 1/thread
    int xrl = tid >> 2;
    int xsp = (xrl < 32) ? s0 : s1;
    uint32_t xsz = (xsp >= 0) ? 16 : 0;
    const __half* xg = Xf
        + (size_t)((xsp >= 0) ? (xsp*32 + (xrl & 31)) : 0) * K + (tid & 3) * 8;
    uint32_t xso = (uint32_t)(xrl*(PADX*2) + (tid & 3)*16);

    // W: thread owns 2 consecutive 16B chunks: row = tid>>3, seg = tid&7
    // (cols seg*8 .. seg*8+7). Swizzle each chunk address independently.
    int wrow = tid >> 3, wseg = tid & 7;
    uint32_t wo    = (uint32_t)(wrow*256 + wseg*32);
    uint32_t wswz0 = SWZ(wo);
    uint32_t wswz1 = SWZ(wo + 16);
    uint32_t cdst  = (uint32_t)(wrow*(PADW*2) + wseg*16);
    const float* wg = W + (size_t)cat * K * HID + (size_t)wrow * HID + n0 + wseg*8;
    const size_t wstep = (size_t)32 * HID;   // per k-tile advance

    int NT = K >> 5;

    // ---- prologue: issue tiles 0 and 1 ----
    #pragma unroll
    for (int pi = 0; pi < 2; pi++) {
        CP16(sb + OX(pi) + xso, xg + pi*32, xsz);
        CP16F(sb + OWF(pi) + wswz0, wg + pi*wstep);
        CP16F(sb + OWF(pi) + wswz1, wg + pi*wstep + 4);
        CP_COMMIT();
    }

    #pragma unroll 1
    for (int it = 0; it < NT; it++) {
        int xs = it % 3;
        int cs = it & 1;

        if (it < NT - 1)
            asm volatile("cp.async.wait_group 1;" ::: "memory");
        else
            asm volatile("cp.async.wait_group 0;" ::: "memory");

        // convert own W chunks (tile it): 2xLDS.128 fp32 -> 1xSTS.128 fp16
        {
            float4 v0 = *reinterpret_cast<const float4*>(smem + OWF(cs) + wswz0);
            float4 v1 = *reinterpret_cast<const float4*>(smem + OWF(cs) + wswz1);
            __half2 h0 = __floats2half2_rn(v0.x, v0.y);
            __half2 h1 = __floats2half2_rn(v0.z, v0.w);
            __half2 h2 = __floats2half2_rn(v1.x, v1.y);
            __half2 h3 = __floats2half2_rn(v1.z, v1.w);
            asm volatile("st.shared.v4.b32 [%0], {%1,%2,%3,%4};"
                         :: "r"(sb + OWC(cs) + cdst),
                            "r"(*reinterpret_cast<uint32_t*>(&h0)),
                            "r"(*reinterpret_cast<uint32_t*>(&h1)),
                            "r"(*reinterpret_cast<uint32_t*>(&h2)),
                            "r"(*reinterpret_cast<uint32_t*>(&h3)) : "memory");
        }
        __syncthreads();

        // prefetch tile it+2
        if (it + 2 < NT) {
            int k0 = (it + 2) << 5;
            CP16(sb + OX((it + 2) % 3) + xso, xg + k0, xsz);
            const float* wsrc = wg + (size_t)(it + 2) * wstep;
            CP16F(sb + OWF(cs) + wswz0, wsrc);
            CP16F(sb + OWF(cs) + wswz1, wsrc + 4);
            CP_COMMIT();
        }

        // compute tile it: warp 32x16, 2 k16 steps
        if (active) {
            #pragma unroll
            for (int ks = 0; ks < 2; ks++) {
                uint32_t a[2][4];
                #pragma unroll
                for (int mt = 0; mt < 2; mt++) {
                    uint32_t aoff = (uint32_t)(OX(xs)
                        + ((mrow*32 + mt*16 + lr15)*PADX + ks*16 + hiK8) * 2);
                    LDSM_X4(a[mt][0],a[mt][1],a[mt][2],a[mt][3], sb + aoff);
                }
                #pragma unroll
                for (int nt = 0; nt < 2; nt++) {
                    uint32_t boff = (uint32_t)(OWC(cs)
                        + ((ks*16 + lr15)*PADW + ncol*16 + nt*8) * 2);
                    uint32_t b0, b1;
                    LDSM_X2T(b0, b1, sb + boff);
                    #pragma unroll
                    for (int mt = 0; mt < 2; mt++)
                        MMA_F16(acc[mt][nt], a[mt][0],a[mt][1],a[mt][2],a[mt][3], b0,b1);
                }
            }
        }
    }

    // ---- epilogue ----
    if (!active) return;
    int r  = lane >> 2;
    int c2 = (lane & 3) * 2;
    #pragma unroll
    for (int mt = 0; mt < 2; mt++) {
        int grow0 = mysamp*32 + mt*16 + r;
        #pragma unroll
        for (int nt = 0; nt < 2; nt++) {
            int col = n0 + ncol*16 + nt*8 + c2;
            float2 bv = *reinterpret_cast<const float2*>(&bias[(size_t)cat*HID + col]);
            float y0 = acc[mt][nt][0] + bv.x;
            float y1 = acc[mt][nt][1] + bv.y;
            float y2 = acc[mt][nt][2] + bv.x;
            float y3 = acc[mt][nt][3] + bv.y;
            if (writeH) {
                y0 = y0 / (1.0f + __expf(-y0));
                y1 = y1 / (1.0f + __expf(-y1));
                y2 = y2 / (1.0f + __expf(-y2));
                y3 = y3 / (1.0f + __expf(-y3));
                __half2 p01 = __floats2half2_rn(y0, y1);
                __half2 p23 = __floats2half2_rn(y2, y3);
                *reinterpret_cast<uint32_t*>(&g_hf[(size_t)grow0*HID + col])
                    = *reinterpret_cast<uint32_t*>(&p01);
                *reinterpret_cast<uint32_t*>(&g_hf[(size_t)(grow0+8)*HID + col])
                    = *reinterpret_cast<uint32_t*>(&p23);
            } else {
                float2 o01 = {y0, y1};
                float2 o23 = {y2, y3};
                *reinterpret_cast<float2*>(&Yf32[(size_t)grow0*HID + col]) = o01;
                *reinterpret_cast<float2*>(&Yf32[(size_t)(grow0+8)*HID + col]) = o23;
            }
        }
    }
}

// ---------------------------------------------------------------------------
extern "C" void kernel_launch(void* const* d_in, const int* in_sizes, int n_in,
                              void* d_out, int out_size)
{
    const float* actions   = (const float*)d_in[0];
    const int*   timesteps = (const int*)  d_in[1];
    const int*   cat_ids   = (const int*)  d_in[2];
    const float* W1        = (const float*)d_in[3];
    const float* b1        = (const float*)d_in[4];
    const float* W2        = (const float*)d_in[5];
    const float* b2        = (const float*)d_in[6];
    const float* W3        = (const float*)d_in[7];
    const float* b3        = (const float*)d_in[8];
    float* out = (float*)d_out;

    __half *xf, *hf;
    cudaGetSymbolAddress((void**)&xf, g_xf);
    cudaGetSymbolAddress((void**)&hf, g_hf);

    static bool attr_set = false;
    if (!attr_set) {
        cudaFuncSetAttribute(gemm_grouped,
                             cudaFuncAttributeMaxDynamicSharedMemorySize, SMEM_BYTES);
        attr_set = true;
    }

    setup_groups<<<1, 32>>>(cat_ids);
    embed_kernel<<<dim3(BB, 3), 256>>>(actions, timesteps, cat_ids, W1, b1);

    // h = swish(x @ W2[cat] + b2) -> fp16
    gemm_grouped<<<dim3(HID/GN, 32), 256, SMEM_BYTES>>>(xf, W2, b2, nullptr, K2, 1);

    // out = h @ W3[cat] + b3 -> fp32
    gemm_grouped<<<dim3(HID/GN, 32), 256, SMEM_BYTES>>>(hf, W3, b3, out, HID, 0);
}

// round 12
// speedup vs baseline: 1.5587x; 1.5587x over previous
#include <cuda_runtime.h>
#include <cuda_fp16.h>
#include <math.h>
#include <stdint.h>

// Problem constants
#define BB 32
#define TT 32
#define AD 32
#define HID 1536
#define K2 (2*HID)   // 3072

// Scratch (__device__ globals)
__device__ __half g_xf[BB*TT*K2];    // concat([a_emb, tau]) fp16
__device__ __half g_hf[BB*TT*HID];   // swish hidden fp16
__device__ int g_gcat[32];
__device__ int g_gsamp[32][2];
__device__ int g_ngroups;

// ---------------------------------------------------------------------------
// Setup: group samples by cat in pairs. One warp.
// ---------------------------------------------------------------------------
__global__ void setup_groups(const int* __restrict__ cats)
{
    __shared__ int sc[32];
    int t = threadIdx.x;
    sc[t] = cats[t];
    __syncwarp();

    unsigned mask = 0;
    #pragma unroll
    for (int s = 0; s < 32; s++)
        if (sc[s] == t) mask |= (1u << s);
    int cnt = __popc(mask);
    int ng  = (cnt + 1) >> 1;

    int incl = ng;
    #pragma unroll
    for (int off = 1; off < 32; off <<= 1) {
        int v = __shfl_up_sync(0xffffffffu, incl, off);
        if (t >= off) incl += v;
    }
    int pre   = incl - ng;
    int total = __shfl_sync(0xffffffffu, incl, 31);
    if (t == 0) g_ngroups = total;

    unsigned m = mask;
    for (int g = 0; g < ng; g++) {
        int slot = pre + g;
        g_gcat[slot] = t;
        #pragma unroll
        for (int j = 0; j < 2; j++) {
            int s = -1;
            if (m) { s = __ffs(m) - 1; m &= m - 1; }
            g_gsamp[slot][j] = s;
        }
    }
    for (int slot = total + t; slot < 32; slot += 32) {
        g_gcat[slot] = -1;
        g_gsamp[slot][0] = -1;
        g_gsamp[slot][1] = -1;
    }
}

// ---------------------------------------------------------------------------
// Kernel 1: x = [actions @ W1[cat] + b1, sinusoidal(ts)] -> fp16
// ---------------------------------------------------------------------------
__global__ __launch_bounds__(256) void embed_kernel(
    const float* __restrict__ actions,
    const int*   __restrict__ timesteps,
    const int*   __restrict__ cats,
    const float* __restrict__ W1,
    const float* __restrict__ b1)
{
    int b = blockIdx.x;
    int p = blockIdx.y * 256 + threadIdx.x;
    int j = 2 * p;

    __shared__ float sa[TT*AD];
    for (int i = threadIdx.x; i < TT*AD; i += 256)
        sa[i] = actions[(size_t)b*TT*AD + i];
    __syncthreads();

    int cat = cats[b];
    const float* Wc = W1 + (size_t)cat * AD * HID;
    float2 bb = *reinterpret_cast<const float2*>(&b1[(size_t)cat*HID + j]);

    float2 wv[AD];
    #pragma unroll
    for (int k = 0; k < AD; k++)
        wv[k] = *reinterpret_cast<const float2*>(&Wc[(size_t)k*HID + j]);

    const float C = -9.210340371976184f / 768.0f;
    float ts = (float)timesteps[b];
    float freq = expf(C * (float)p);
    float s, c;
    sincosf(ts * freq, &s, &c);
    __half2 tp = __floats2half2_rn(s, c);
    uint32_t tu = *reinterpret_cast<uint32_t*>(&tp);

    #pragma unroll 4
    for (int t = 0; t < TT; t++) {
        float a0 = bb.x, a1 = bb.y;
        #pragma unroll
        for (int k = 0; k < AD; k++) {
            float av = sa[t*AD + k];
            a0 += av * wv[k].x;
            a1 += av * wv[k].y;
        }
        size_t row = (size_t)(b*TT + t) * K2;
        __half2 ap = __floats2half2_rn(a0, a1);
        *reinterpret_cast<uint32_t*>(&g_xf[row + j]) = *reinterpret_cast<uint32_t*>(&ap);
        *reinterpret_cast<uint32_t*>(&g_xf[row + HID + j]) = tu;
    }
}

// ---------------------------------------------------------------------------
// Grouped fp16 mma.sync GEMM.
// CTA: M=64 (2 samples, one cat) x N=128, K-tile 32. 8 warps, warp = 32r x 32c
//   (mrow = warp&1; ncol = warp>>1 in 0..3 -> cols ncol*32..+31).
// X fp16: 3-stage cp.async ring (pad-40 rows) — R9 staging pattern.
// W fp32: 2-stage cp.async ring, 512B contiguous rows (no swizzle needed:
//   every warp instruction covers 512B contiguous). Each thread converts the
//   4 chunks it loaded (LDS.128 -> STS.64) into sWc (2-stage, pad-136 rows).
// ONE __syncthreads per k-tile. 3 CTAs/SM (smem 64KB).
// ---------------------------------------------------------------------------
#define GN    128
#define PADX  40
#define PADW  136
#define XELEM (64*PADX)          // 2560 fp16 per stage
#define WFS   (32*GN)            // 4096 fp32 per stage (512B rows, contiguous)
#define WCS   (32*PADW)          // 4352 fp16 per stage
#define OX(s)   ((s)*(XELEM*2))                 // 3 x 5120   -> [0, 15360)
#define OWF(s)  (15360 + (s)*(WFS*4))           // 2 x 16384  -> [15360, 48128)
#define OWC(s)  (48128 + (s)*(WCS*2))           // 2 x 8704   -> [48128, 65536)
#define SMEM_BYTES 65536

#define MMA_F16(d, a0,a1,a2,a3, b0,b1) \
  asm volatile("mma.sync.aligned.m16n8k16.row.col.f32.f16.f16.f32 " \
               "{%0,%1,%2,%3}, {%4,%5,%6,%7}, {%8,%9}, {%0,%1,%2,%3};" \
               : "+f"(d[0]),"+f"(d[1]),"+f"(d[2]),"+f"(d[3]) \
               : "r"(a0),"r"(a1),"r"(a2),"r"(a3),"r"(b0),"r"(b1))

#define LDSM_X4(r0,r1,r2,r3, addr) \
  asm volatile("ldmatrix.sync.aligned.m8n8.x4.shared.b16 {%0,%1,%2,%3}, [%4];" \
               : "=r"(r0),"=r"(r1),"=r"(r2),"=r"(r3) : "r"(addr))

#define LDSM_X2T(r0,r1, addr) \
  asm volatile("ldmatrix.sync.aligned.m8n8.x2.trans.shared.b16 {%0,%1}, [%2];" \
               : "=r"(r0),"=r"(r1) : "r"(addr))

#define CP16(sa, ga, sz) \
  asm volatile("cp.async.ca.shared.global [%0], [%1], 16, %2;" \
               :: "r"(sa), "l"(ga), "r"(sz))
#define CP16F(sa, ga) \
  asm volatile("cp.async.ca.shared.global [%0], [%1], 16;" :: "r"(sa), "l"(ga))
#define CP_COMMIT() asm volatile("cp.async.commit_group;" ::: "memory")

__global__ __launch_bounds__(256,3) void gemm_grouped(
    const __half* __restrict__ Xf,
    const float* __restrict__ W,
    const float* __restrict__ bias,
    float* __restrict__ Yf32,
    int K, int writeH)
{
    if ((int)blockIdx.y >= g_ngroups) return;

    extern __shared__ char smem[];
    uint32_t sb;
    asm("{ .reg .u64 t; cvta.to.shared.u64 t, %1; cvt.u32.u64 %0, t; }"
        : "=r"(sb) : "l"(smem));

    int slot = blockIdx.y;
    int cat  = g_gcat[slot];
    int s0 = g_gsamp[slot][0];
    int s1 = g_gsamp[slot][1];

    int n0 = blockIdx.x * GN;

    int tid  = threadIdx.x;
    int lane = tid & 31;
    int warp = tid >> 5;
    int mrow = warp & 1;      // sample half: rows mrow*32..+31
    int ncol = warp >> 1;     // 32-col slice: cols ncol*32..+31

    int lr15 = lane & 15;
    int hiK8 = ((lane >> 4) & 1) * 8;
    int mysamp = mrow ? s1 : s0;
    bool active = (mysamp >= 0);

    float acc[2][4][4];
    #pragma unroll
    for (int mt = 0; mt < 2; mt++)
        #pragma unroll
        for (int nt = 0; nt < 4; nt++)
            #pragma unroll
            for (int j = 0; j < 4; j++) acc[mt][nt][j] = 0.0f;

    // ---- staging geometry (R9 pattern, fully coalesced) ----
    // X: 64 rows x 32 k fp16 = 256 x 16B chunks, 1/thread
    int xrl = tid >> 2;
    int xsp = (xrl < 32) ? s0 : s1;
    uint32_t xsz = (xsp >= 0) ? 16 : 0;
    const __half* xg = Xf
        + (size_t)((xsp >= 0) ? (xsp*32 + (xrl & 31)) : 0) * K + (tid & 3) * 8;
    uint32_t xso = (uint32_t)(xrl*(PADX*2) + (tid & 3)*16);

    // W fp32: 32 k x 128 n = 1024 x 16B chunks, 4/thread.
    // chunk c: row = c*8 + warp, col-chunk = lane (warp covers 512B contiguous)
    const float* wg = W + (size_t)cat * K * HID + (size_t)warp * HID + n0 + lane*4;
    const size_t wrstep = (size_t)8 * HID;     // +8 rows per chunk index
    const size_t wstep  = (size_t)32 * HID;    // per k-tile advance
    // smem fp32 offset for chunk c: (c*8+warp)*512 + lane*16
    uint32_t wfo = (uint32_t)(warp*512 + lane*16);   // + c*4096
    // convert dst (fp16): (c*8+warp)*PADW*2 + lane*8
    uint32_t wco = (uint32_t)(warp*(PADW*2) + lane*8);  // + c*8*PADW*2

    int NT = K >> 5;

    // ---- prologue: issue tiles 0 and 1 ----
    #pragma unroll
    for (int pi = 0; pi < 2; pi++) {
        CP16(sb + OX(pi) + xso, xg + pi*32, xsz);
        #pragma unroll
        for (int c = 0; c < 4; c++)
            CP16F(sb + OWF(pi) + wfo + c*4096, wg + pi*wstep + c*wrstep);
        CP_COMMIT();
    }

    #pragma unroll 1
    for (int it = 0; it < NT; it++) {
        int xs = it % 3;
        int cs = it & 1;

        if (it < NT - 1)
            asm volatile("cp.async.wait_group 1;" ::: "memory");
        else
            asm volatile("cp.async.wait_group 0;" ::: "memory");

        // convert own W chunks (tile it): 4 x (LDS.128 fp32 -> STS.64 fp16)
        #pragma unroll
        for (int c = 0; c < 4; c++) {
            float4 v = *reinterpret_cast<const float4*>(smem + OWF(cs) + wfo + c*4096);
            __half2 h0 = __floats2half2_rn(v.x, v.y);
            __half2 h1 = __floats2half2_rn(v.z, v.w);
            asm volatile("st.shared.v2.b32 [%0], {%1,%2};"
                         :: "r"(sb + OWC(cs) + wco + c*(8*PADW*2)),
                            "r"(*reinterpret_cast<uint32_t*>(&h0)),
                            "r"(*reinterpret_cast<uint32_t*>(&h1)) : "memory");
        }
        __syncthreads();

        // prefetch tile it+2
        if (it + 2 < NT) {
            int k0 = (it + 2) << 5;
            CP16(sb + OX((it + 2) % 3) + xso, xg + k0, xsz);
            const float* wsrc = wg + (size_t)(it + 2) * wstep;
            #pragma unroll
            for (int c = 0; c < 4; c++)
                CP16F(sb + OWF(cs) + wfo + c*4096, wsrc + c*wrstep);
            CP_COMMIT();
        }

        // compute tile it: warp 32x32, 2 k16 steps
        if (active) {
            #pragma unroll
            for (int ks = 0; ks < 2; ks++) {
                uint32_t a[2][4];
                #pragma unroll
                for (int mt = 0; mt < 2; mt++) {
                    uint32_t aoff = (uint32_t)(OX(xs)
                        + ((mrow*32 + mt*16 + lr15)*PADX + ks*16 + hiK8) * 2);
                    LDSM_X4(a[mt][0],a[mt][1],a[mt][2],a[mt][3], sb + aoff);
                }
                #pragma unroll
                for (int nt = 0; nt < 4; nt++) {
                    uint32_t boff = (uint32_t)(OWC(cs)
                        + ((ks*16 + lr15)*PADW + ncol*32 + nt*8) * 2);
                    uint32_t b0, b1;
                    LDSM_X2T(b0, b1, sb + boff);
                    #pragma unroll
                    for (int mt = 0; mt < 2; mt++)
                        MMA_F16(acc[mt][nt], a[mt][0],a[mt][1],a[mt][2],a[mt][3], b0,b1);
                }
            }
        }
    }

    // ---- epilogue ----
    if (!active) return;
    int r  = lane >> 2;
    int c2 = (lane & 3) * 2;
    #pragma unroll
    for (int mt = 0; mt < 2; mt++) {
        int grow0 = mysamp*32 + mt*16 + r;
        #pragma unroll
        for (int nt = 0; nt < 4; nt++) {
            int col = n0 + ncol*32 + nt*8 + c2;
            float2 bv = *reinterpret_cast<const float2*>(&bias[(size_t)cat*HID + col]);
            float y0 = acc[mt][nt][0] + bv.x;
            float y1 = acc[mt][nt][1] + bv.y;
            float y2 = acc[mt][nt][2] + bv.x;
            float y3 = acc[mt][nt][3] + bv.y;
            if (writeH) {
                y0 = y0 / (1.0f + __expf(-y0));
                y1 = y1 / (1.0f + __expf(-y1));
                y2 = y2 / (1.0f + __expf(-y2));
                y3 = y3 / (1.0f + __expf(-y3));
                __half2 p01 = __floats2half2_rn(y0, y1);
                __half2 p23 = __floats2half2_rn(y2, y3);
                *reinterpret_cast<uint32_t*>(&g_hf[(size_t)grow0*HID + col])
                    = *reinterpret_cast<uint32_t*>(&p01);
                *reinterpret_cast<uint32_t*>(&g_hf[(size_t)(grow0+8)*HID + col])
                    = *reinterpret_cast<uint32_t*>(&p23);
            } else {
                float2 o01 = {y0, y1};
                float2 o23 = {y2, y3};
                *reinterpret_cast<float2*>(&Yf32[(size_t)grow0*HID + col]) = o01;
                *reinterpret_cast<float2*>(&Yf32[(size_t)(grow0+8)*HID + col]) = o23;
            }
        }
    }
}

// ---------------------------------------------------------------------------
extern "C" void kernel_launch(void* const* d_in, const int* in_sizes, int n_in,
                              void* d_out, int out_size)
{
    const float* actions   = (const float*)d_in[0];
    const int*   timesteps = (const int*)  d_in[1];
    const int*   cat_ids   = (const int*)  d_in[2];
    const float* W1        = (const float*)d_in[3];
    const float* b1        = (const float*)d_in[4];
    const float* W2        = (const float*)d_in[5];
    const float* b2        = (const float*)d_in[6];
    const float* W3        = (const float*)d_in[7];
    const float* b3        = (const float*)d_in[8];
    float* out = (float*)d_out;

    __half *xf, *hf;
    cudaGetSymbolAddress((void**)&xf, g_xf);
    cudaGetSymbolAddress((void**)&hf, g_hf);

    static bool attr_set = false;
    if (!attr_set) {
        cudaFuncSetAttribute(gemm_grouped,
                             cudaFuncAttributeMaxDynamicSharedMemorySize, SMEM_BYTES);
        attr_set = true;
    }

    setup_groups<<<1, 32>>>(cat_ids);
    embed_kernel<<<dim3(BB, 3), 256>>>(actions, timesteps, cat_ids, W1, b1);

    // h = swish(x @ W2[cat] + b2) -> fp16
    gemm_grouped<<<dim3(HID/GN, 32), 256, SMEM_BYTES>>>(xf, W2, b2, nullptr, K2, 1);

    // out = h @ W3[cat] + b3 -> fp32
    gemm_grouped<<<dim3(HID/GN, 32), 256, SMEM_BYTES>>>(hf, W3, b3, out, HID, 0);
}